// round 3
// baseline (speedup 1.0000x reference)
#include <cuda_runtime.h>
#include <cuda_bf16.h>

// Problem dims (fixed by setup_inputs)
#define T_DIM 2048
#define N_DIM 128
#define C_DIM 96
#define L_DIM 200
#define S_EXT 401          // 2*L+1
#define NWARP 13
#define NTHR  (NWARP * 32) // 416: one state per thread (401 real + 15 dummy)
#define PF    8            // log-prob register prefetch depth (power of 2)
#define D_RING 16          // boundary ring depth (power of 2)
#define NEGF  (-1.0e30f)   // log-domain 'zero' (absorption-safe in fp32)
#define LOG2E 1.44269504088896340736f
#define LN2   0.69314718055994530942f

__device__ float g_loss[N_DIM];

__device__ __forceinline__ unsigned ld_acquire_cta(unsigned* p) {
    unsigned v;
    asm volatile("ld.acquire.cta.b32 %0, [%1];" : "=r"(v) : "l"(p) : "memory");
    return v;
}
__device__ __forceinline__ void st_release_cta(unsigned* p, unsigned v) {
    asm volatile("st.release.cta.b32 [%0], %1;" :: "l"(p), "r"(v) : "memory");
}

// One CTA per batch element. Log2-domain CTC forward, warp-pipelined wavefront:
// no block barrier in the main loop; warp w consumes warp w-1's 2 boundary
// states via an acquire/release SMEM ring.
__global__ __launch_bounds__(NTHR, 1)
void ctc_forward_kernel(const float* __restrict__ predicts,   // (T, N, C)
                        const int*   __restrict__ labels,     // (N, L)
                        const int*   __restrict__ preds_lengths,
                        const int*   __restrict__ label_lengths)
{
    const int s    = threadIdx.x;
    const int n    = blockIdx.x;
    const int w    = s >> 5;
    const int lane = s & 31;

    __shared__ float2   bring[D_RING][NWARP]; // boundary (a[32w+30], a[32w+31]) per tick slot
    __shared__ unsigned pflag[NWARP];         // completed ticks per warp
    __shared__ float    Fin[2];

    // init ring/flags
    for (int i = s; i < D_RING * NWARP; i += NTHR)
        ((float2*)bring)[i] = make_float2(NEGF, NEGF);
    if (s < NWARP) pflag[s] = 0u;
    __syncthreads();

    // Extended label per state: even s -> blank(0), odd s -> labels[n][(s-1)/2].
    int  ext  = 0;
    bool skip = false;
    if ((s & 1) && s < S_EXT) {
        const int k = s >> 1;
        ext = labels[n * L_DIM + k];
        if (s >= 3) skip = (ext != labels[n * L_DIM + k - 1]);
    }
    const int src_lane = ext & 31;
    const int src_slot = ext >> 5;           // 0..2 (classes 0..95)
    const int len = preds_lengths[n];
    const int end = 2 * label_lengths[n];

    // Coalesced per-warp row prefetch: lane holds classes lane, lane+32, lane+64.
    const float* __restrict__ lpb = predicts + (size_t)n * C_DIM + lane;
    float rA[PF], rB[PF], rC[PF];
#pragma unroll
    for (int j = 0; j < PF; ++j) {
        const size_t o = (size_t)j * (N_DIM * C_DIM);
        rA[j] = __ldg(lpb + o);
        rB[j] = __ldg(lpb + o + 32);
        rC[j] = __ldg(lpb + o + 64);
    }

    // log2-alpha, with virtual alpha_{-1}: 0 at s=0.
    float a = (s == 0) ? 0.0f : NEGF;

    unsigned prod_seen = 0u;                                   // flag[w-1] cache
    int      cons_ok   = (w == NWARP - 1) ? 0x7fffffff : (D_RING - 2);
    bool     done      = false;

    for (int tt = 0; tt < T_DIM && !done; tt += PF) {
#pragma unroll
        for (int j = 0; j < PF; ++j) {
            const int t = tt + j;

            // gather lp[ext] for tick t from the register-resident row
            const float vA = __shfl_sync(0xffffffffu, rA[j], src_lane);
            const float vB = __shfl_sync(0xffffffffu, rB[j], src_lane);
            const float vC = __shfl_sync(0xffffffffu, rC[j], src_lane);
            const float lpe = ((src_slot == 0) ? vA : (src_slot == 1) ? vB : vC) * LOG2E;

            // prefetch row t+PF
            const int tn = t + PF;
            if (tn < T_DIM) {
                const size_t o = (size_t)tn * (N_DIM * C_DIM);
                rA[j] = __ldg(lpb + o);
                rB[j] = __ldg(lpb + o + 32);
                rC[j] = __ldg(lpb + o + 64);
            }

            // intra-warp neighbors
            float am1 = __shfl_up_sync(0xffffffffu, a, 1);
            float am2 = __shfl_up_sync(0xffffffffu, a, 2);

            // warp boundary from warp w-1 (tick t-1)
            float2 bnd = make_float2(NEGF, NEGF);
            if (w > 0) {
                while ((int)prod_seen < t)
                    prod_seen = ld_acquire_cta(&pflag[w - 1]);
                bnd = bring[(t - 1) & (D_RING - 1)][w - 1];
            }
            if (lane == 0) { am1 = bnd.y; am2 = bnd.x; }
            if (lane == 1) { am2 = bnd.y; }

            // a = logaddexp2(a, am1, skip?am2:-inf) + lpe
            am2 = skip ? am2 : NEGF;
            const float m   = fmaxf(fmaxf(a, am1), am2);
            const float sum = exp2f(a - m) + exp2f(am1 - m) + exp2f(am2 - m);
            a = m + __log2f(sum) + lpe;
            if (s >= S_EXT) a = NEGF;   // keep dummy states silent

            // backpressure: don't overwrite a slot the consumer still needs
            if (t > cons_ok) {
                unsigned f;
                do { f = ld_acquire_cta(&pflag[w + 1]); }
                while ((int)f + (D_RING - 2) < t);
                cons_ok = (int)f + (D_RING - 2);
            }

            // publish boundary + release flag (single thread => ordered)
            const float a30 = __shfl_sync(0xffffffffu, a, 30);
            if (lane == 31) {
                bring[t & (D_RING - 1)][w] = make_float2(a30, a);
                st_release_cta(&pflag[w], (unsigned)(t + 1));
            }

            if (t == len - 1) {
                if (s == end)     Fin[0] = a;
                if (s == end - 1) Fin[1] = a;
                done = true;
                break;
            }
        }
    }

    __syncthreads();
    if (s == 0) {
        const float f0 = Fin[0], f1 = Fin[1];
        const float mm   = fmaxf(f0, f1);
        const float fin2 = mm + __log2f(exp2f(f0 - mm) + exp2f(f1 - mm));
        const float ctc  = -(fin2 * LN2);
        const float fw   = 1.0f - __expf(-ctc);     // focal: alpha=1, gamma=2
        g_loss[n] = ctc * (fw * fw);
    }
}

// Reduce the 128 per-batch focal-weighted losses to the scalar output.
__global__ void ctc_finalize_kernel(float* __restrict__ out)
{
    const int i = threadIdx.x;
    float v = g_loss[i];
#pragma unroll
    for (int off = 16; off; off >>= 1)
        v += __shfl_xor_sync(0xffffffffu, v, off);
    __shared__ float ws[4];
    if ((i & 31) == 0) ws[i >> 5] = v;
    __syncthreads();
    if (i == 0) out[0] = ws[0] + ws[1] + ws[2] + ws[3];
}

extern "C" void kernel_launch(void* const* d_in, const int* in_sizes, int n_in,
                              void* d_out, int out_size)
{
    const float* predicts      = (const float*)d_in[0];
    const int*   labels        = (const int*)  d_in[1];
    // d_in[2] = ref_labels (unused), d_in[5] = ref_length (unused)
    const int*   preds_lengths = (const int*)  d_in[3];
    const int*   label_lengths = (const int*)  d_in[4];
    float*       out           = (float*)d_out;

    ctc_forward_kernel<<<N_DIM, NTHR>>>(predicts, labels, preds_lengths, label_lengths);
    ctc_finalize_kernel<<<1, N_DIM>>>(out);
}

// round 4
// speedup vs baseline: 2.8791x; 2.8791x over previous
#include <cuda_runtime.h>
#include <cuda_bf16.h>

// Problem dims (fixed by setup_inputs)
#define T_DIM 2048
#define N_DIM 128
#define C_DIM 96
#define NC    (N_DIM * C_DIM)
#define L_DIM 200
#define S_EXT 401          // 2*L+1
#define NWARP 8
#define NTHR  (NWARP * 32) // 256
#define KWIN  4            // ticks per halo window (= barrier period)
#define OWN   56           // owned slots per warp
#define HALO  8            // left halo slots per warp (= 2*KWIN)
#define NSLOT (NWARP * OWN)        // 448 total slots (>= 401 states)
#define NPAIR ((NSLOT + HALO) / 2) // 228 float2 exchange slots
#define NEGF  (-1.0e30f)   // log-domain 'zero'
#define LOG2E 1.44269504088896340736f
#define LN2   0.69314718055994530942f

__device__ float g_loss[N_DIM];

static __device__ __forceinline__ float ex2f_(float x) {
    float r; asm("ex2.approx.ftz.f32 %0, %1;" : "=f"(r) : "f"(x)); return r;
}
static __device__ __forceinline__ float lg2f_(float x) {
    float r; asm("lg2.approx.ftz.f32 %0, %1;" : "=f"(r) : "f"(x)); return r;
}

// One CTA per batch element. Log2-domain CTC forward.
// Halo-redundant windows: each warp carries a 2*KWIN left halo so KWIN ticks
// run with intra-warp shuffles only; one __syncthreads per window refreshes
// halos and flips the staged log-prob buffer. Even states (blanks) use a
// 2-input logsumexp, odd states a 3-input sorted form (5 MUFU / thread-pair).
__global__ __launch_bounds__(NTHR, 1)
void ctc_forward_kernel(const float* __restrict__ predicts,   // (T, N, C)
                        const int*   __restrict__ labels,     // (N, L)
                        const int*   __restrict__ preds_lengths,
                        const int*   __restrict__ label_lengths)
{
    const int tid  = threadIdx.x;
    const int n    = blockIdx.x;
    const int w    = tid >> 5;
    const int lane = tid & 31;
    const int s0   = OWN * w - HALO + 2 * lane;  // even slot
    const int s1   = s0 + 1;                     // odd slot
    const bool own = (lane >= HALO / 2);         // lanes 0..3 hold halo only

    __shared__ float2 As[2][NPAIR];   // ping-pong halo-exchange buffers
    __shared__ float  Lp[2 * 8 * C_DIM];  // double-buffered 8-tick log2-prob windows
    __shared__ float  Fin[2];

    if (tid < HALO / 2) {             // permanent -inf pads for slots < 0
        As[0][tid] = make_float2(NEGF, NEGF);
        As[1][tid] = make_float2(NEGF, NEGF);
    }

    // Odd slot s1 carries label ext; even slots are blanks (class 0, no skip).
    int  ext1  = 0;
    bool skip1 = false;
    if (s1 >= 1 && s1 < S_EXT) {
        const int k = s1 >> 1;
        ext1 = labels[n * L_DIM + k];
        if (s1 >= 3) skip1 = (ext1 != labels[n * L_DIM + k - 1]);
    }
    const int len = preds_lengths[n];
    const int end = 2 * label_lengths[n];

    // Cooperative staging geometry: 8 rows x 96 classes = 768 floats, 3/thread.
    const float* gptr[3]; int r_q[3];
#pragma unroll
    for (int q = 0; q < 3; ++q) {
        const int idx = tid + q * NTHR;
        const int r = idx / C_DIM, c = idx - r * C_DIM;
        r_q[q]  = r;
        gptr[q] = predicts + (size_t)r * NC + (size_t)n * C_DIM + c;
    }
    // Pre-stage rows [0,8) into buffer 0 (already converted to log2).
#pragma unroll
    for (int q = 0; q < 3; ++q)
        Lp[tid + q * NTHR] = __ldg(gptr[q]) * LOG2E;
    __syncthreads();

    // log2-alpha with virtual alpha_{-1}: 0 at slot 0, -inf elsewhere.
    float a0 = (s0 == 0) ? 0.0f : NEGF;
    float a1 = NEGF;
    float stg[3];
    const int pidx = (s0 + HALO) >> 1;
    const int nwin = (len + KWIN - 1) >> 2;   // uniform per CTA -> safe early exit

    for (int win = 0; win < nwin; ++win) {
        const int t0 = win << 2;
        const float* lrow_base = Lp + (((win >> 1) & 1) ? 768 : 0);

        // Even window: issue LDGs for rows [t0+8, t0+16) (consumed 2 windows later).
        if (!(win & 1)) {
#pragma unroll
            for (int q = 0; q < 3; ++q) {
                const int t = t0 + 8 + r_q[q];
                stg[q] = (t < T_DIM) ? __ldg(gptr[q] + (size_t)(t0 + 8) * NC) : 0.0f;
            }
        }

#pragma unroll
        for (int j = 0; j < KWIN; ++j) {
            const int t = t0 + j;
            const float* lrow = lrow_base + (t & 7) * C_DIM;
            const float lp0 = lrow[0];      // blank: broadcast LDS
            const float lp1 = lrow[ext1];   // gather LDS

            float sh1 = __shfl_up_sync(0xffffffffu, a1, 1);  // slot s0-1 == s1-2
            if (lane == 0) sh1 = NEGF;

            // even state (blank): logaddexp2(a0, sh1)
            const float x0  = fminf(a0, sh1), y0 = fmaxf(a0, sh1);
            const float na0 = y0 + lg2f_(1.0f + ex2f_(x0 - y0)) + lp0;

            // odd state: logaddexp2(a1, a0_old, skip ? sh1 : -inf), sorted form
            const float p2  = skip1 ? sh1 : NEGF;
            const float x   = fminf(a1, a0), y = fmaxf(a1, a0);
            const float m   = fmaxf(y, p2);
            const float mid = fmaxf(x, fminf(y, p2));
            const float lo  = fminf(x, p2);
            const float na1 = m + lg2f_(1.0f + ex2f_(mid - m) + ex2f_(lo - m)) + lp1;

            a0 = na0; a1 = na1;

            if (t == len - 1 && own) {       // record final states (owners only)
                if (s0 == end)     Fin[0] = a0;
                if (s0 == end - 1) Fin[1] = a0;
                if (s1 == end - 1) Fin[1] = a1;
            }
        }

        // Odd window: commit staged rows (DRAM latency long gone by now).
        if (win & 1) {
            float* dst = Lp + ((((win >> 1) + 1) & 1) ? 768 : 0);
#pragma unroll
            for (int q = 0; q < 3; ++q)
                dst[tid + q * NTHR] = stg[q] * LOG2E;
        }

        // Halo refresh: owners publish, everyone reloads (ping-pong => 1 barrier).
        const int ab = win & 1;
        if (own) As[ab][pidx] = make_float2(a0, a1);
        __syncthreads();
        const float2 v = As[ab][pidx];
        a0 = v.x; a1 = v.y;
    }

    __syncthreads();
    if (tid == 0) {
        const float f0 = Fin[0], f1 = Fin[1];
        const float mm   = fmaxf(f0, f1);
        const float fin2 = mm + lg2f_(ex2f_(f0 - mm) + ex2f_(f1 - mm));
        const float ctc  = -(fin2 * LN2);
        const float fw   = 1.0f - expf(-ctc);   // focal: alpha=1, gamma=2
        g_loss[n] = ctc * (fw * fw);
    }
}

// Reduce the 128 per-batch focal-weighted losses to the scalar output.
__global__ void ctc_finalize_kernel(float* __restrict__ out)
{
    const int i = threadIdx.x;
    float v = g_loss[i];
#pragma unroll
    for (int off = 16; off; off >>= 1)
        v += __shfl_xor_sync(0xffffffffu, v, off);
    __shared__ float ws[4];
    if ((i & 31) == 0) ws[i >> 5] = v;
    __syncthreads();
    if (i == 0) out[0] = ws[0] + ws[1] + ws[2] + ws[3];
}

extern "C" void kernel_launch(void* const* d_in, const int* in_sizes, int n_in,
                              void* d_out, int out_size)
{
    const float* predicts      = (const float*)d_in[0];
    const int*   labels        = (const int*)  d_in[1];
    // d_in[2] = ref_labels (unused), d_in[5] = ref_length (unused)
    const int*   preds_lengths = (const int*)  d_in[3];
    const int*   label_lengths = (const int*)  d_in[4];
    float*       out           = (float*)d_out;

    ctc_forward_kernel<<<N_DIM, NTHR>>>(predicts, labels, preds_lengths, label_lengths);
    ctc_finalize_kernel<<<1, N_DIM>>>(out);
}

// round 5
// speedup vs baseline: 3.3569x; 1.1659x over previous
#include <cuda_runtime.h>
#include <cuda_bf16.h>

// Problem dims (fixed by setup_inputs)
#define T_DIM 2048
#define N_DIM 128
#define C_DIM 96
#define NC    (N_DIM * C_DIM)
#define L_DIM 200
#define S_EXT 401          // 2*L+1
#define NWARP 8
#define NTHR  (NWARP * 32) // 256
#define KWIN  4            // ticks per halo window (= barrier period)
#define OWN   56           // owned slots per warp
#define HALO  8            // left halo slots per warp (= 2*KWIN)
#define NSLOT (NWARP * OWN)        // 448 slots (>= 401 states)
#define NPAIR ((NSLOT + HALO) / 2) // 228 pair records
#define LN2   0.69314718055994530942f

__device__ float g_loss[N_DIM];

// One CTA per batch element. CTC forward in per-pair block-floating-point:
// each thread owns 2 adjacent states (even=blank, odd=label) as linear floats
// (v0,v1) plus an integer power-of-two scale iM. The tick update is pure FMA
// (no MUFU in the recurrence); probs are linearized once per row at staging.
// Halo-redundant 4-tick windows: one __syncthreads per window renormalizes,
// exchanges halos, and rebuilds the fixed per-window neighbor rescale fp.
__global__ __launch_bounds__(NTHR, 1)
void ctc_forward_kernel(const float* __restrict__ predicts,   // (T, N, C)
                        const int*   __restrict__ labels,     // (N, L)
                        const int*   __restrict__ preds_lengths,
                        const int*   __restrict__ label_lengths)
{
    const int tid  = threadIdx.x;
    const int n    = blockIdx.x;
    const int w    = tid >> 5;
    const int lane = tid & 31;
    const int s0   = OWN * w - HALO + 2 * lane;  // even slot
    const int s1   = s0 + 1;                     // odd slot
    const bool own = (lane >= HALO / 2);
    const int pidx = (s0 + HALO) >> 1;           // 28*w + lane

    __shared__ float4 As[2][NPAIR];       // (v0, v1, iM-as-float, pad)
    __shared__ float  Pb[2 * 8 * C_DIM];  // linear probs, double-buffered 8 rows
    __shared__ float  FinV[2];
    __shared__ int    FinI[2];

    if (tid < HALO / 2) {                 // permanent zero-pads for slots < 0
        As[0][tid] = make_float4(0.f, 0.f, __int_as_float(0), 0.f);
        As[1][tid] = make_float4(0.f, 0.f, __int_as_float(0), 0.f);
    }

    // Odd slot s1 carries label ext; even slots are blanks (no skip).
    int   ext1 = 0;
    float skf  = 0.0f;
    if (s1 >= 1 && s1 < S_EXT) {
        const int k = s1 >> 1;
        ext1 = labels[n * L_DIM + k];
        if (s1 >= 3) skf = (ext1 != labels[n * L_DIM + k - 1]) ? 1.0f : 0.0f;
    }
    const int len = preds_lengths[n];
    const int end = 2 * label_lengths[n];

    // Cooperative staging: 8 rows x 96 classes = 768 floats, 3 per thread.
    const float* gptr[3]; int r_q[3];
#pragma unroll
    for (int q = 0; q < 3; ++q) {
        const int idx = tid + q * NTHR;
        const int r = idx / C_DIM, c = idx - r * C_DIM;
        r_q[q]  = r;
        gptr[q] = predicts + (size_t)r * NC + (size_t)n * C_DIM + c;
    }
    // Pre-stage rows [0,8) as LINEAR probs into buffer 0.
#pragma unroll
    for (int q = 0; q < 3; ++q)
        Pb[tid + q * NTHR] = __expf(__ldg(gptr[q]));
    __syncthreads();

    float v0 = (s0 == 0) ? 1.0f : 0.0f;   // virtual alpha_{-1}: 1 at slot 0
    float v1 = 0.0f;
    int   iM = 0;
    float fp = (lane == 0) ? 0.0f : 1.0f; // all scales equal at t=0
    float stg[3];
    const int nwin = (len + KWIN - 1) >> 2;   // len uniform per CTA

    for (int win = 0; win < nwin; ++win) {
        const int t0 = win << 2;

        // Even window: issue LDGs for rows [t0+8, t0+16) (consumed 2 windows on).
        if (!(win & 1)) {
#pragma unroll
            for (int q = 0; q < 3; ++q) {
                const int t = t0 + 8 + r_q[q];
                stg[q] = (t < T_DIM) ? __ldg(gptr[q] + (size_t)(t0 + 8) * NC) : 0.0f;
            }
        }

        const float* prow = Pb + (((win >> 1) & 1) ? 768 : 0) + (t0 & 7) * C_DIM;
#pragma unroll
        for (int j = 0; j < KWIN; ++j) {
            const int t = t0 + j;
            const float P0 = prow[0];
            const float P1 = prow[ext1];

            float vp1  = __shfl_up_sync(0xffffffffu, v1, 1);
            float vp1r = vp1 * fp;                       // fp==0 masks lane 0

            const float nv0 = (v0 + vp1r) * P0;          // blank state
            const float nv1 = (v1 + v0 + vp1r * skf) * P1;
            v0 = nv0; v1 = nv1;
            prow += C_DIM;

            if (t == len - 1 && own) {
                if (s0 == end)     { FinV[0] = v0; FinI[0] = iM; }
                if (s1 == end - 1) { FinV[1] = v1; FinI[1] = iM; }
            }
        }

        // Odd window: commit staged rows as linear probs (LDGs long complete).
        if (win & 1) {
            float* dst = Pb + ((((win >> 1) + 1) & 1) ? 768 : 0);
#pragma unroll
            for (int q = 0; q < 3; ++q)
                dst[tid + q * NTHR] = __expf(stg[q]);
        }

        // ---- window boundary ----
        // 1) per-pair renorm: pull exponent of max(v0,v1) into iM.
        const float mx = fmaxf(v0, v1);
        if (mx > 0.0f) {
            const int e = (int)(__float_as_uint(mx) >> 23) - 127;
            iM += e;
            const float sc = __int_as_float((unsigned)(127 - e) << 23);
            v0 *= sc; v1 *= sc;
        }
        // 2) owners publish; barrier; everyone reloads their pair.
        const int ab = win & 1;
        if (own) As[ab][pidx] = make_float4(v0, v1, __int_as_float(iM), 0.f);
        __syncthreads();
        const float4 pv = As[ab][pidx];
        v0 = pv.x; v1 = pv.y; iM = __float_as_int(pv.z);

        // 3) unreached pairs adopt a propagated scale (4 pairs back, via SMEM).
        if (v0 == 0.0f && v1 == 0.0f)
            iM = __float_as_int(As[ab][(pidx >= 4) ? (pidx - 4) : 0].z);

        // 4) fixed per-window neighbor rescale factor from post-adoption scales.
        const int iMp = __shfl_up_sync(0xffffffffu, iM, 1);
        int k = iMp - iM;
        k = (k > 120) ? 120 : ((k < -127) ? -127 : k);
        fp = __int_as_float((unsigned)(k + 127) << 23);  // k=-127 -> exact 0
        if (lane == 0) fp = 0.0f;
    }

    __syncthreads();
    if (tid == 0) {
        const float f0 = __log2f(FinV[0]) + (float)FinI[0];
        const float f1 = __log2f(FinV[1]) + (float)FinI[1];
        const float mm   = fmaxf(f0, f1);
        const float fin2 = mm + __log2f(exp2f(f0 - mm) + exp2f(f1 - mm));
        const float ctc  = -(fin2 * LN2);
        const float fw   = 1.0f - __expf(-ctc);     // focal: alpha=1, gamma=2
        g_loss[n] = ctc * (fw * fw);
    }
}

// Reduce the 128 per-batch focal-weighted losses to the scalar output.
__global__ void ctc_finalize_kernel(float* __restrict__ out)
{
    const int i = threadIdx.x;
    float v = g_loss[i];
#pragma unroll
    for (int off = 16; off; off >>= 1)
        v += __shfl_xor_sync(0xffffffffu, v, off);
    __shared__ float ws[4];
    if ((i & 31) == 0) ws[i >> 5] = v;
    __syncthreads();
    if (i == 0) out[0] = ws[0] + ws[1] + ws[2] + ws[3];
}

extern "C" void kernel_launch(void* const* d_in, const int* in_sizes, int n_in,
                              void* d_out, int out_size)
{
    const float* predicts      = (const float*)d_in[0];
    const int*   labels        = (const int*)  d_in[1];
    // d_in[2] = ref_labels (unused), d_in[5] = ref_length (unused)
    const int*   preds_lengths = (const int*)  d_in[3];
    const int*   label_lengths = (const int*)  d_in[4];
    float*       out           = (float*)d_out;

    ctc_forward_kernel<<<N_DIM, NTHR>>>(predicts, labels, preds_lengths, label_lengths);
    ctc_finalize_kernel<<<1, N_DIM>>>(out);
}